// round 1
// baseline (speedup 1.0000x reference)
#include <cuda_runtime.h>
#include <math.h>

// Problem constants (shape variant fixed by dataset)
#define NH 6
#define NN 64   // rows of A tile (n)
#define NK 64   // inner dim (k)  == A channels per head
#define ND 30   // cols of B tile (d) == B channels per head
#define NDP 32  // padded d

// ---------------- scratch (device globals; no allocations allowed) ----------
__device__ float g_amin[NH*NK], g_amax[NH*NK];
__device__ float g_bmin[NH*ND], g_bmax[NH*ND];
__device__ float g_dA[NH*NK], g_zA[NH*NK], g_iA[NH*NK];
__device__ float g_dB[NH*ND], g_zB[NH*ND], g_iB[NH*ND];

// ---------------- float atomic min/max via int/uint ordering ----------------
__device__ __forceinline__ void atomicMaxF(float* addr, float v) {
    if (v >= 0.0f) atomicMax((int*)addr, __float_as_int(v));
    else           atomicMin((unsigned int*)addr, __float_as_uint(v));
}
__device__ __forceinline__ void atomicMinF(float* addr, float v) {
    if (v >= 0.0f) atomicMin((int*)addr, __float_as_int(v));
    else           atomicMax((unsigned int*)addr, __float_as_uint(v));
}

// ---------------- kernel 0: init minmax scratch ------------------------------
__global__ void k_init() {
    int i = threadIdx.x;
    if (i < NH*NK) { g_amin[i] =  INFINITY; g_amax[i] = -INFINITY; }
    if (i < NH*ND) { g_bmin[i] =  INFINITY; g_bmax[i] = -INFINITY; }
}

// ---------------- kernel 1a: min/max of A over (b,n) per (h,k) ---------------
// grid (NH, nby), block 256. Each block: fixed h, bpb batch slices.
__global__ __launch_bounds__(256) void k_minmax_A(const float* __restrict__ A,
                                                  int batch, int bpb) {
    int h  = blockIdx.x;
    int b0 = blockIdx.y * bpb;
    int t  = threadIdx.x;
    int k0 = (t & 15) * 4;          // this thread's 4 k-channels (fixed)
    float4 mn = make_float4( INFINITY,  INFINITY,  INFINITY,  INFINITY);
    float4 mx = make_float4(-INFINITY, -INFINITY, -INFINITY, -INFINITY);
    for (int bi = 0; bi < bpb; ++bi) {
        int b = b0 + bi;
        if (b >= batch) break;
        const float4* p = (const float4*)(A + ((size_t)b * NH + h) * (NN*NK));
        #pragma unroll
        for (int it = 0; it < 4; ++it) {
            float4 v = p[it * 256 + t];   // k = 4*(t&15)+j for all it (1024%64==0)
            mn.x = fminf(mn.x, v.x); mx.x = fmaxf(mx.x, v.x);
            mn.y = fminf(mn.y, v.y); mx.y = fmaxf(mx.y, v.y);
            mn.z = fminf(mn.z, v.z); mx.z = fmaxf(mx.z, v.z);
            mn.w = fminf(mn.w, v.w); mx.w = fmaxf(mx.w, v.w);
        }
    }
    __shared__ float smn[64*17], smx[64*17];
    int col = t >> 4;                 // 0..15
    smn[(k0+0)*17 + col] = mn.x; smx[(k0+0)*17 + col] = mx.x;
    smn[(k0+1)*17 + col] = mn.y; smx[(k0+1)*17 + col] = mx.y;
    smn[(k0+2)*17 + col] = mn.z; smx[(k0+2)*17 + col] = mx.z;
    smn[(k0+3)*17 + col] = mn.w; smx[(k0+3)*17 + col] = mx.w;
    __syncthreads();
    if (t < 64) {
        float a = INFINITY, b = -INFINITY;
        #pragma unroll
        for (int c = 0; c < 16; ++c) {
            a = fminf(a, smn[t*17 + c]);
            b = fmaxf(b, smx[t*17 + c]);
        }
        atomicMinF(&g_amin[h*NK + t], a);
        atomicMaxF(&g_amax[h*NK + t], b);
    }
}

// ---------------- kernel 1b: min/max of B over (b,k) per (h,d) ---------------
// grid (NH, nby), block 480. thread t: d = t%30 fixed, kk = t/30.
__global__ __launch_bounds__(480) void k_minmax_B(const float* __restrict__ B,
                                                  int batch, int bpb) {
    int h  = blockIdx.x;
    int b0 = blockIdx.y * bpb;
    int t  = threadIdx.x;
    float mn = INFINITY, mx = -INFINITY;
    for (int bi = 0; bi < bpb; ++bi) {
        int b = b0 + bi;
        if (b >= batch) break;
        const float* p = B + ((size_t)b * NH + h) * (NK*ND);
        #pragma unroll
        for (int it = 0; it < 4; ++it) {
            float v = p[it * 480 + t];    // d = t%30 for all it (480%30==0)
            mn = fminf(mn, v); mx = fmaxf(mx, v);
        }
    }
    __shared__ float smn[30*17], smx[30*17];
    int d = t % 30, g = t / 30;        // g in [0,16)
    smn[d*17 + g] = mn; smx[d*17 + g] = mx;
    __syncthreads();
    if (t < 30) {
        float a = INFINITY, b = -INFINITY;
        #pragma unroll
        for (int c = 0; c < 16; ++c) {
            a = fminf(a, smn[t*17 + c]);
            b = fmaxf(b, smx[t*17 + c]);
        }
        atomicMinF(&g_bmin[h*ND + t], a);
        atomicMaxF(&g_bmax[h*ND + t], b);
    }
}

// ---------------- kernel 2: per-channel quant params -------------------------
__global__ void k_params() {
    int i = threadIdx.x;
    if (i < NH*NK) {
        float mn = g_amin[i], mx = g_amax[i];
        float d  = fmaxf((mx - mn) * (1.0f/255.0f), 1e-8f);
        // match reference: delta = max((xmax-xmin)/255, 1e-8) with true division
        d = fmaxf((mx - mn) / 255.0f, 1e-8f);
        float z = rintf(-mn / d);
        g_dA[i] = d; g_zA[i] = z; g_iA[i] = 1.0f / d;
    }
    if (i < NH*ND) {
        float mn = g_bmin[i], mx = g_bmax[i];
        float d  = fmaxf((mx - mn) / 255.0f, 1e-8f);
        float z = rintf(-mn / d);
        g_dB[i] = d; g_zB[i] = z; g_iB[i] = 1.0f / d;
    }
}

// fake-quant one value; fast path uses reciprocal, borderline rescued by
// correctly-rounded division so ties match the reference's x/delta exactly.
__device__ __forceinline__ float fq(float x, float dlt, float zp, float inv) {
    float y = x * inv;
    float r = rintf(y);
    if (fabsf(fabsf(y - r) - 0.5f) < 1e-4f) r = rintf(x / dlt);
    float q = fminf(fmaxf(r + zp, 0.0f), 255.0f);
    return (q - zp) * dlt;
}

// ---------------- kernel 3: quantize-on-load + 64x64 @ 64x30 matmul ----------
// one block per (b,h) slice; 256 threads.
// As: k-major [k][n] with XOR swizzle (units of 2 cols) -> conflict-free
// transpose-store AND conflict-free float2 compute reads.
// Bs: [k][32] padded, float4 compute reads.
__global__ __launch_bounds__(256) void k_qmm(const float* __restrict__ A,
                                             const float* __restrict__ B,
                                             float* __restrict__ C) {
    int s = blockIdx.x;          // slice = b*NH + h
    int h = s % NH;
    int t = threadIdx.x;

    __shared__ float As[NK * NN];     // 16 KB, swizzled
    __shared__ float Bs[NK * NDP];    // 8 KB
    __shared__ float pA[3 * NK];      // dA, zA, iA
    __shared__ float pB[3 * NDP];

    if (t < NK) {
        pA[t]        = g_dA[h*NK + t];
        pA[NK + t]   = g_zA[h*NK + t];
        pA[2*NK + t] = g_iA[h*NK + t];
    } else if (t < NK + NDP) {
        int d = t - NK;
        if (d < ND) {
            pB[d]         = g_dB[h*ND + d];
            pB[NDP + d]   = g_zB[h*ND + d];
            pB[2*NDP + d] = g_iB[h*ND + d];
        } else {
            pB[d] = 1.0f; pB[NDP + d] = 0.0f; pB[2*NDP + d] = 1.0f;
        }
    }
    if (t < 128) {                      // zero the 2 padded B columns
        int k = t >> 1, d = ND + (t & 1);
        Bs[k * NDP + d] = 0.0f;
    }
    __syncthreads();

    // ---- load + quantize A (float4, transpose-store with swizzle) ----
    const float4* Ap = (const float4*)(A + (size_t)s * (NN*NK));
    #pragma unroll
    for (int it = 0; it < 4; ++it) {
        float4 v = Ap[it * 256 + t];
        int e  = (it * 256 + t) * 4;
        int n  = e >> 6;
        int k0 = e & 63;
        float q[4] = {v.x, v.y, v.z, v.w};
        #pragma unroll
        for (int j = 0; j < 4; ++j) {
            int k = k0 + j;
            float val = fq(q[j], pA[k], pA[NK + k], pA[2*NK + k]);
            int swz = 2 * ((k >> 2) & 15);
            As[k * NN + (n ^ swz)] = val;
        }
    }
    // ---- load + quantize B ----
    const float* Bp = B + (size_t)s * (NK*ND);
    #pragma unroll
    for (int it = 0; it < 8; ++it) {
        int e = it * 256 + t;
        if (e < NK*ND) {
            int k = e / ND, d = e % ND;
            float val = fq(Bp[e], pB[d], pB[NDP + d], pB[2*NDP + d]);
            Bs[k * NDP + d] = val;
        }
    }
    __syncthreads();

    // ---- compute: thread = 2 rows x 4 cols register tile ----
    int rg = t >> 3;     // 0..31 -> rows 2rg, 2rg+1
    int dg = t & 7;      // 0..7  -> cols 4dg..4dg+3
    float a00=0,a01=0,a02=0,a03=0;
    float a10=0,a11=0,a12=0,a13=0;
    #pragma unroll 16
    for (int k = 0; k < NK; ++k) {
        float4 bv = *(const float4*)&Bs[k * NDP + dg * 4];
        int swz = 2 * ((k >> 2) & 15);
        float2 av = *(const float2*)&As[k * NN + ((2*rg) ^ swz)];
        a00 += av.x * bv.x; a01 += av.x * bv.y; a02 += av.x * bv.z; a03 += av.x * bv.w;
        a10 += av.y * bv.x; a11 += av.y * bv.y; a12 += av.y * bv.z; a13 += av.y * bv.w;
    }

    // ---- write C[64][30] ----
    float* Cp = C + (size_t)s * (NN*ND);
    int n0 = 2 * rg, c0 = 4 * dg;
    float r0[4] = {a00,a01,a02,a03};
    float r1[4] = {a10,a11,a12,a13};
    #pragma unroll
    for (int j = 0; j < 4; ++j) {
        int d = c0 + j;
        if (d < ND) {
            Cp[n0 * ND + d]       = r0[j];
            Cp[(n0 + 1) * ND + d] = r1[j];
        }
    }
}

// ---------------- launch -----------------------------------------------------
extern "C" void kernel_launch(void* const* d_in, const int* in_sizes, int n_in,
                              void* d_out, int out_size) {
    const float* A = (const float*)d_in[0];
    const float* B = (const float*)d_in[1];
    float* C = (float*)d_out;

    int batch  = in_sizes[0] / (NH * NN * NK);   // 4096
    int slices = batch * NH;                     // 24576

    k_init<<<1, 384>>>();

    int bpbA = 32;
    int nbyA = (batch + bpbA - 1) / bpbA;        // 128
    k_minmax_A<<<dim3(NH, nbyA), 256>>>(A, batch, bpbA);

    int bpbB = 64;
    int nbyB = (batch + bpbB - 1) / bpbB;        // 64
    k_minmax_B<<<dim3(NH, nbyB), 480>>>(B, batch, bpbB);

    k_params<<<1, 384>>>();

    k_qmm<<<slices, 256>>>(A, B, C);
}

// round 5
// speedup vs baseline: 1.1929x; 1.1929x over previous
#include <cuda_runtime.h>
#include <cuda_bf16.h>
#include <math.h>
#include <stdint.h>

// Problem constants
#define NH 6
#define NN 64   // rows of A tile (n)
#define NK 64   // inner dim (k)
#define ND 30   // cols of B tile (d)

// ---------------- scratch (device globals) -----------------------------------
__device__ __align__(16) float g_amin[NH*NK], g_amax[NH*NK];
__device__ __align__(16) float g_bmin[NH*ND], g_bmax[NH*ND];
__device__ __align__(16) float g_dA[NH*NK], g_zA[NH*NK], g_iA[NH*NK];
__device__ __align__(16) float g_dB[NH*ND], g_zB[NH*ND], g_iB[NH*ND];

// ---------------- float atomic min/max via int/uint ordering -----------------
__device__ __forceinline__ void atomicMaxF(float* addr, float v) {
    if (v >= 0.0f) atomicMax((int*)addr, __float_as_int(v));
    else           atomicMin((unsigned int*)addr, __float_as_uint(v));
}
__device__ __forceinline__ void atomicMinF(float* addr, float v) {
    if (v >= 0.0f) atomicMin((int*)addr, __float_as_int(v));
    else           atomicMax((unsigned int*)addr, __float_as_uint(v));
}

// ---------------- small PTX helpers (all base-target legal) ------------------
__device__ __forceinline__ uint32_t smem_to_u32(const void* p) {
    uint32_t a;
    asm("{ .reg .u64 tmp; cvta.to.shared.u64 tmp, %1; cvt.u32.u64 %0, tmp; }"
        : "=r"(a) : "l"(p));
    return a;
}
__device__ __forceinline__ void ldsm_x4(uint32_t* r, uint32_t addr) {
    asm volatile("ldmatrix.sync.aligned.m8n8.x4.shared.b16 {%0,%1,%2,%3}, [%4];"
                 : "=r"(r[0]), "=r"(r[1]), "=r"(r[2]), "=r"(r[3]) : "r"(addr));
}
__device__ __forceinline__ void mma_bf16(float* c, const uint32_t* a,
                                         const uint32_t* b) {
    asm volatile(
        "mma.sync.aligned.m16n8k16.row.col.f32.bf16.bf16.f32 "
        "{%0,%1,%2,%3}, {%4,%5,%6,%7}, {%8,%9}, {%0,%1,%2,%3};"
        : "+f"(c[0]), "+f"(c[1]), "+f"(c[2]), "+f"(c[3])
        : "r"(a[0]), "r"(a[1]), "r"(a[2]), "r"(a[3]), "r"(b[0]), "r"(b[1]));
}
#define SWZ128(off) ((off) ^ (((off) >> 3) & 0x70))

// ---------------- kernel 0: init minmax scratch ------------------------------
__global__ void k_init() {
    int i = threadIdx.x;
    if (i < NH*NK) { g_amin[i] =  INFINITY; g_amax[i] = -INFINITY; }
    if (i < NH*ND) { g_bmin[i] =  INFINITY; g_bmax[i] = -INFINITY; }
}

// ---------------- kernel 1a: min/max of A ------------------------------------
__global__ __launch_bounds__(256) void k_minmax_A(const float* __restrict__ A,
                                                  int batch, int bpb) {
    int h  = blockIdx.x;
    int b0 = blockIdx.y * bpb;
    int t  = threadIdx.x;
    int k0 = (t & 15) * 4;
    float4 mn = make_float4( INFINITY,  INFINITY,  INFINITY,  INFINITY);
    float4 mx = make_float4(-INFINITY, -INFINITY, -INFINITY, -INFINITY);
    for (int bi = 0; bi < bpb; ++bi) {
        int b = b0 + bi;
        if (b >= batch) break;
        const float4* p = (const float4*)(A + ((size_t)b * NH + h) * (NN*NK));
        #pragma unroll
        for (int it = 0; it < 4; ++it) {
            float4 v = p[it * 256 + t];
            mn.x = fminf(mn.x, v.x); mx.x = fmaxf(mx.x, v.x);
            mn.y = fminf(mn.y, v.y); mx.y = fmaxf(mx.y, v.y);
            mn.z = fminf(mn.z, v.z); mx.z = fmaxf(mx.z, v.z);
            mn.w = fminf(mn.w, v.w); mx.w = fmaxf(mx.w, v.w);
        }
    }
    __shared__ float smn[64*17], smx[64*17];
    int col = t >> 4;
    smn[(k0+0)*17 + col] = mn.x; smx[(k0+0)*17 + col] = mx.x;
    smn[(k0+1)*17 + col] = mn.y; smx[(k0+1)*17 + col] = mx.y;
    smn[(k0+2)*17 + col] = mn.z; smx[(k0+2)*17 + col] = mx.z;
    smn[(k0+3)*17 + col] = mn.w; smx[(k0+3)*17 + col] = mx.w;
    __syncthreads();
    if (t < 64) {
        float a = INFINITY, b = -INFINITY;
        #pragma unroll
        for (int c = 0; c < 16; ++c) {
            a = fminf(a, smn[t*17 + c]);
            b = fmaxf(b, smx[t*17 + c]);
        }
        atomicMinF(&g_amin[h*NK + t], a);
        atomicMaxF(&g_amax[h*NK + t], b);
    }
}

// ---------------- kernel 1b: min/max of B ------------------------------------
__global__ __launch_bounds__(480) void k_minmax_B(const float* __restrict__ B,
                                                  int batch, int bpb) {
    int h  = blockIdx.x;
    int b0 = blockIdx.y * bpb;
    int t  = threadIdx.x;
    float mn = INFINITY, mx = -INFINITY;
    for (int bi = 0; bi < bpb; ++bi) {
        int b = b0 + bi;
        if (b >= batch) break;
        const float* p = B + ((size_t)b * NH + h) * (NK*ND);
        #pragma unroll
        for (int it = 0; it < 4; ++it) {
            float v = p[it * 480 + t];
            mn = fminf(mn, v); mx = fmaxf(mx, v);
        }
    }
    __shared__ float smn[30*17], smx[30*17];
    int d = t % 30, g = t / 30;
    smn[d*17 + g] = mn; smx[d*17 + g] = mx;
    __syncthreads();
    if (t < 30) {
        float a = INFINITY, b = -INFINITY;
        #pragma unroll
        for (int c = 0; c < 16; ++c) {
            a = fminf(a, smn[t*17 + c]);
            b = fmaxf(b, smx[t*17 + c]);
        }
        atomicMinF(&g_bmin[h*ND + t], a);
        atomicMaxF(&g_bmax[h*ND + t], b);
    }
}

// ---------------- kernel 2: per-channel quant params -------------------------
__global__ void k_params() {
    int i = threadIdx.x;
    if (i < NH*NK) {
        float mn = g_amin[i], mx = g_amax[i];
        float d = fmaxf((mx - mn) / 255.0f, 1e-8f);
        float z = rintf(-mn / d);
        g_dA[i] = d; g_zA[i] = z; g_iA[i] = 1.0f / d;
    }
    if (i < NH*ND) {
        float mn = g_bmin[i], mx = g_bmax[i];
        float d = fmaxf((mx - mn) / 255.0f, 1e-8f);
        float z = rintf(-mn / d);
        g_dB[i] = d; g_zB[i] = z; g_iB[i] = 1.0f / d;
    }
}

// fake-quant returning (q-zp)*delta; fast reciprocal path, tie rescue by
// correctly-rounded division
__device__ __forceinline__ float fq(float x, float dlt, float zp, float inv) {
    float y = x * inv;
    float r = rintf(y);
    if (fabsf(fabsf(y - r) - 0.5f) < 1e-4f) r = rintf(x / dlt);
    float q = fminf(fmaxf(r + zp, 0.0f), 255.0f);
    return (q - zp) * dlt;
}
// fake-quant returning the integer (q-zp)  (exact in bf16, |v| <= 255)
__device__ __forceinline__ float fqi(float x, float dlt, float zp, float inv) {
    float y = x * inv;
    float r = rintf(y);
    if (fabsf(fabsf(y - r) - 0.5f) < 1e-4f) r = rintf(x / dlt);
    return fminf(fmaxf(r + zp, 0.0f), 255.0f) - zp;
}

__device__ __forceinline__ unsigned pack_bf16(__nv_bfloat16 lo, __nv_bfloat16 hi) {
    return (unsigned)__bfloat16_as_ushort(lo) | ((unsigned)__bfloat16_as_ushort(hi) << 16);
}

// ---------------- per-slice smem layout (bytes) ------------------------------
// Ahi: 64 rows x 128B (bf16, SW128 swizzled)  = 8192
// Alo: 8192
// Bt : 32 rows (d) x 128B (bf16 int values, SW128) = 4096   (rows 30,31 unused)
#define OFF_AHI 0
#define OFF_ALO 8192
#define OFF_BT  16384
#define SLICE_BYTES 20480
#define SMEM_DYN (2*SLICE_BYTES + 1024)

// ---------------- kernel 3: bf16 hi/lo split MMA quantized matmul ------------
// One block per PAIR of (b,h) slices. 256 threads = 8 warps; warps 0-3 work on
// slice 0, warps 4-7 on slice 1. Warp ws handles rows 16*ws..16*ws+15, all 32
// (padded) output columns. D = (A'hi + A'lo) @ Bint, scaled by dB[d] at the end.
__global__ __launch_bounds__(256)
void k_qmm_mma(const float* __restrict__ A, const float* __restrict__ B,
               float* __restrict__ C) {
    extern __shared__ char raw[];
    char* sm = (char*)(((uintptr_t)raw + 1023) & ~(uintptr_t)1023);
    uint32_t sb = smem_to_u32(sm);

    int t = threadIdx.x;
    int p = blockIdx.x;
    int s0 = 2 * p;
    int h0 = s0 % NH, h1 = (s0 + 1) % NH;

    // ---- A: quantize, hi/lo split, transpose-free swizzled store ----
    const float4* Ap = (const float4*)(A + (size_t)s0 * (NN*NK));
    #pragma unroll
    for (int it = 0; it < 8; ++it) {
        int idx = it * 256 + t;
        float4 v = Ap[idx];
        int j  = idx >> 10;                 // slice within pair
        int e  = (idx & 1023) * 4;
        int m  = e >> 6, k0 = e & 63;
        int hb = (j ? h1 : h0) * NK + k0;
        float4 d4 = __ldg((const float4*)&g_dA[hb]);
        float4 z4 = __ldg((const float4*)&g_zA[hb]);
        float4 i4 = __ldg((const float4*)&g_iA[hb]);
        float q0 = fq(v.x, d4.x, z4.x, i4.x);
        float q1 = fq(v.y, d4.y, z4.y, i4.y);
        float q2 = fq(v.z, d4.z, z4.z, i4.z);
        float q3 = fq(v.w, d4.w, z4.w, i4.w);
        __nv_bfloat16 h0b = __float2bfloat16(q0), h1b = __float2bfloat16(q1);
        __nv_bfloat16 h2b = __float2bfloat16(q2), h3b = __float2bfloat16(q3);
        __nv_bfloat16 l0b = __float2bfloat16(q0 - __bfloat162float(h0b));
        __nv_bfloat16 l1b = __float2bfloat16(q1 - __bfloat162float(h1b));
        __nv_bfloat16 l2b = __float2bfloat16(q2 - __bfloat162float(h2b));
        __nv_bfloat16 l3b = __float2bfloat16(q3 - __bfloat162float(h3b));
        uint32_t off = SWZ128((uint32_t)(m * 128 + k0 * 2));
        char* base = sm + j * SLICE_BYTES;
        *(uint2*)(base + OFF_AHI + off) =
            make_uint2(pack_bf16(h0b, h1b), pack_bf16(h2b, h3b));
        *(uint2*)(base + OFF_ALO + off) =
            make_uint2(pack_bf16(l0b, l1b), pack_bf16(l2b, l3b));
    }

    // ---- B: quantize to exact bf16 integers, transpose-store [d][k] ----
    const float* Bp = B + (size_t)s0 * (NK*ND);
    #pragma unroll
    for (int it = 0; it < 15; ++it) {
        int e = it * 256 + t;
        float x = Bp[e];
        int j  = (e >= NK*ND);
        int e2 = e - j * (NK*ND);
        int k  = e2 / ND, d = e2 % ND;
        int hb = (j ? h1 : h0) * ND + d;
        float bi = fqi(x, __ldg(&g_dB[hb]), __ldg(&g_zB[hb]), __ldg(&g_iB[hb]));
        uint32_t off = SWZ128((uint32_t)(d * 128 + k * 2));
        *(__nv_bfloat16*)(sm + j * SLICE_BYTES + OFF_BT + off) =
            __float2bfloat16(bi);
    }
    __syncthreads();

    // ---- compute: warp = 16 rows x 32 cols, mma.sync m16n8k16 bf16 ----
    int w = t >> 5, lane = t & 31;
    int sj = w >> 2;          // slice
    int ws = w & 3;           // warp within slice
    int r0 = ws * 16;
    uint32_t baseS = sb + sj * SLICE_BYTES;

    int la = lane & 7, lb = (lane >> 3) & 1, lc = (lane >> 4) & 1;
    // A x4: lanes 0-7 rows r0+0..7 @k0 | 8-15 rows r0+8..15 @k0 |
    //       16-23 rows r0+0..7 @k0+8 | 24-31 rows r0+8..15 @k0+8
    uint32_t aRel = (uint32_t)((r0 + la + lb * 8) * 128 + lc * 16);
    // B x4: lanes 0-7 rows d0..7 @k0 | 8-15 rows d0..7 @k0+8 |
    //       16-23 rows d0+8..15 @k0 | 24-31 rows d0+8..15 @k0+8
    uint32_t bRel = (uint32_t)((la + lc * 8) * 128 + lb * 16);

    float acc[4][4];
    #pragma unroll
    for (int i = 0; i < 4; ++i)
        #pragma unroll
        for (int q = 0; q < 4; ++q) acc[i][q] = 0.0f;

    #pragma unroll
    for (int kt = 0; kt < 4; ++kt) {
        uint32_t ko = kt * 32;
        uint32_t ah[4], al[4], b0[4], b1[4];
        uint32_t ao = SWZ128(aRel + ko);
        ldsm_x4(ah, baseS + OFF_AHI + ao);
        ldsm_x4(al, baseS + OFF_ALO + ao);
        ldsm_x4(b0, baseS + OFF_BT + SWZ128(bRel + ko));            // d0 = 0,8
        ldsm_x4(b1, baseS + OFF_BT + SWZ128(bRel + 2048 + ko));     // d0 = 16,24
        mma_bf16(acc[0], ah, b0 + 0); mma_bf16(acc[0], al, b0 + 0);
        mma_bf16(acc[1], ah, b0 + 2); mma_bf16(acc[1], al, b0 + 2);
        mma_bf16(acc[2], ah, b1 + 0); mma_bf16(acc[2], al, b1 + 0);
        mma_bf16(acc[3], ah, b1 + 2); mma_bf16(acc[3], al, b1 + 2);
    }

    // ---- epilogue: scale by dB[d], write C ----
    int s  = s0 + sj;
    int h  = s % NH;
    int row = r0 + (lane >> 2);
    int dd  = 2 * (lane & 3);
    float* Cp = C + (size_t)s * (NN*ND);
    #pragma unroll
    for (int nt = 0; nt < 4; ++nt) {
        int d = nt * 8 + dd;
        if (d < ND) {
            float sc0 = __ldg(&g_dB[h*ND + d]);
            Cp[row * ND + d]       = acc[nt][0] * sc0;
            Cp[(row + 8) * ND + d] = acc[nt][2] * sc0;
            if (d + 1 < ND) {
                float sc1 = __ldg(&g_dB[h*ND + d + 1]);
                Cp[row * ND + d + 1]       = acc[nt][1] * sc1;
                Cp[(row + 8) * ND + d + 1] = acc[nt][3] * sc1;
            }
        }
    }
}

// ---------------- launch -----------------------------------------------------
extern "C" void kernel_launch(void* const* d_in, const int* in_sizes, int n_in,
                              void* d_out, int out_size) {
    const float* A = (const float*)d_in[0];
    const float* B = (const float*)d_in[1];
    float* C = (float*)d_out;

    int batch  = in_sizes[0] / (NH * NN * NK);   // 4096
    int npairs = batch * NH / 2;                 // 12288

    k_init<<<1, 384>>>();

    int bpbA = 32;
    int nbyA = (batch + bpbA - 1) / bpbA;
    k_minmax_A<<<dim3(NH, nbyA), 256>>>(A, batch, bpbA);

    int bpbB = 64;
    int nbyB = (batch + bpbB - 1) / bpbB;
    k_minmax_B<<<dim3(NH, nbyB), 480>>>(B, batch, bpbB);

    k_params<<<1, 384>>>();

    k_qmm_mma<<<npairs, 256, SMEM_DYN>>>(A, B, C);
}